// round 2
// baseline (speedup 1.0000x reference)
#include <cuda_runtime.h>
#include <math.h>

// FARGAN vocoder: 100 frames x 4 subframes sequential recurrence, B=64 independent.
// One CTA per batch element; all state in shared memory; weights streamed from L2.

#define NT 256

namespace {
constexpr int S      = 64;
constexpr int NSUB   = 4;
constexpr int L      = 512;
constexpr int F      = 193;
constexpr int BATCH  = 64;
constexpr int FRAMES = 100;
constexpr int OUT_PER_B = FRAMES * NSUB * S;  // 25600
}

struct Smem {
    float ring[512];    // prev samples ring buffer
    float x[256];       // frame input
    float c1[256];
    float c2[256];
    float c[512];       // frame conditioning
    float vin[388];     // subframe fw input
    float fwt[64];      // tanh(fw pre-glu)
    float gi[192];
    float gh[192];
    float xg[128];      // GRU input [cur, prev_sub]
    float skip[320];    // [o1,o2,o3,fw,prev_sub]
    float sd[128];
    float tmp[128];
    float outv[64];
    float s1[64], s2[64], s3[64];
    float sfw[128];
};

__device__ __forceinline__ float sigm(float v) {
    return 1.0f / (1.0f + __expf(-v));
}

// out[o] = act( sum_i W[o*I + i] * v[i] ), W row-major (O x I), v/out in smem.
// ACT: 0 = identity, 1 = tanh
template<int O, int I, int ACT>
__device__ __forceinline__ void matvec(const float* __restrict__ W,
                                       const float* __restrict__ v,
                                       float* __restrict__ out, int tid) {
    constexpr int P   = (NT / O) >= 4 ? 4 : ((NT / O) >= 2 ? 2 : 1);
    constexpr int RPP = NT / P;           // rows per pass
    constexpr int NV  = I / 4;            // float4s per row (all I are %4==0)
    const float4* __restrict__ W4 = reinterpret_cast<const float4*>(W);
    const float4* __restrict__ v4 = reinterpret_cast<const float4*>(v);

    const int part = tid % P;
    #pragma unroll
    for (int r0 = 0; r0 < O; r0 += RPP) {
        int row = r0 + tid / P;
        if ((O % RPP != 0) && row >= O) break;
        const float4* __restrict__ wr = W4 + (long)row * NV;
        float4 acc = make_float4(0.f, 0.f, 0.f, 0.f);
        #pragma unroll 4
        for (int j = part; j < NV; j += P) {
            float4 w = wr[j];
            float4 a = v4[j];
            acc.x += w.x * a.x;
            acc.y += w.y * a.y;
            acc.z += w.z * a.z;
            acc.w += w.w * a.w;
        }
        float s = (acc.x + acc.y) + (acc.z + acc.w);
        if (P > 1) {
            #pragma unroll
            for (int m = 1; m < P; m <<= 1)
                s += __shfl_xor_sync(0xffffffffu, s, m);
        }
        if (part == 0) out[row] = (ACT == 1) ? tanhf(s) : s;
    }
}

// One GRU stage + GLU. Writes new state into `state`, gated output into
// skip[skip_off..skip_off+64) and xg[0..64) (input slot for next stage).
__device__ __forceinline__ void gru_glu(const float* __restrict__ Wih,
                                        const float* __restrict__ Whh,
                                        const float* __restrict__ Wg,
                                        float* __restrict__ state,
                                        Smem& sm, int skip_off, int tid) {
    matvec<192, 128, 0>(Wih, sm.xg, sm.gi, tid);
    matvec<192,  64, 0>(Whh, state, sm.gh, tid);
    __syncthreads();
    if (tid < 64) {
        float r = sigm(sm.gi[tid]       + sm.gh[tid]);
        float z = sigm(sm.gi[64 + tid]  + sm.gh[64 + tid]);
        float n = tanhf(sm.gi[128 + tid] + r * sm.gh[128 + tid]);
        state[tid] = (1.0f - z) * n + z * state[tid];
    }
    __syncthreads();
    matvec<64, 64, 0>(Wg, state, sm.tmp, tid);
    __syncthreads();
    if (tid < 64) {
        float o = state[tid] * sigm(sm.tmp[tid]);
        sm.skip[skip_off + tid] = o;
        sm.xg[tid] = o;
    }
    __syncthreads();
}

__global__ void __launch_bounds__(NT, 1)
fargan_kernel(const float* __restrict__ features,
              const float* __restrict__ gfeat,
              const float* __restrict__ prev0,
              const float* __restrict__ Wc1,  const float* __restrict__ Wc2,
              const float* __restrict__ Wc3,  const float* __restrict__ Wfw,
              const float* __restrict__ Wfwg, const float* __restrict__ Wih1,
              const float* __restrict__ Whh1, const float* __restrict__ Wih2,
              const float* __restrict__ Whh2, const float* __restrict__ Wih3,
              const float* __restrict__ Whh3, const float* __restrict__ Wg1,
              const float* __restrict__ Wg2,  const float* __restrict__ Wg3,
              const float* __restrict__ Wsg,  const float* __restrict__ Wsd,
              const float* __restrict__ Wout,
              float* __restrict__ out) {
    __shared__ Smem sm;
    const int b   = blockIdx.x;
    const int tid = threadIdx.x;

    // init state
    for (int i = tid; i < 512; i += NT) sm.ring[i] = prev0[b * 512 + i];
    if (tid < 64) { sm.s1[tid] = 0.f; sm.s2[tid] = 0.f; sm.s3[tid] = 0.f; }
    if (tid < 128) sm.sfw[tid] = 0.f;
    int head = 0;
    __syncthreads();

    const float* featb = features + (long)b * F * FRAMES;

    for (int t = 0; t < FRAMES; t++) {
        // ---- frame conditioning ----
        if (tid < 192) sm.x[tid] = featb[tid * FRAMES + t];
        else           sm.x[tid] = gfeat[b * 64 + (tid - 192)];
        int period = __float2int_rn(featb[192 * FRAMES + t]);
        __syncthreads();

        matvec<256, 256, 1>(Wc1, sm.x,  sm.c1, tid); __syncthreads();
        matvec<256, 256, 1>(Wc2, sm.c1, sm.c2, tid); __syncthreads();
        matvec<512, 256, 1>(Wc3, sm.c2, sm.c,  tid); __syncthreads();

        for (int k = 0; k < NSUB; k++) {
            // ---- build vin = [feat2s(128), prev_sub(64), lookback(68), sfw(128)] ----
            if (tid < 128) {
                sm.vin[tid]       = sm.c[tid * 4 + k];   // feat2s
                sm.vin[260 + tid] = sm.sfw[tid];
            }
            if (tid < 64) {
                float p = sm.ring[(head + 448 + tid) & 511];  // prev_sub
                sm.vin[128 + tid]  = p;
                sm.xg[64 + tid]    = p;
                sm.skip[256 + tid] = p;
            }
            if (tid >= 64 && tid < 132) {
                int i = tid - 64;
                int idx = L - period + i - 2;
                if (idx >= L) idx -= period;
                sm.vin[192 + i] = sm.ring[(head + idx) & 511];
            }
            __syncthreads();

            // ---- fw = glu(tanh(vin @ Wfw^T), Wfw_g) ----
            matvec<64, 388, 1>(Wfw, sm.vin, sm.fwt, tid); __syncthreads();
            matvec<64,  64, 0>(Wfwg, sm.fwt, sm.tmp, tid); __syncthreads();
            if (tid < 64) {
                float fwv = sm.fwt[tid] * sigm(sm.tmp[tid]);
                sm.xg[tid]         = fwv;
                sm.skip[192 + tid] = fwv;
            }
            __syncthreads();

            // ---- three GRU + GLU stages ----
            gru_glu(Wih1, Whh1, Wg1, sm.s1, sm, 0,   tid);
            gru_glu(Wih2, Whh2, Wg2, sm.s2, sm, 64,  tid);
            gru_glu(Wih3, Whh3, Wg3, sm.s3, sm, 128, tid);

            // ---- skip path ----
            matvec<128, 320, 1>(Wsd, sm.skip, sm.sd, tid); __syncthreads();
            matvec<128, 128, 0>(Wsg, sm.sd, sm.tmp, tid);  __syncthreads();
            if (tid < 128) sm.sd[tid] = sm.sd[tid] * sigm(sm.tmp[tid]);
            __syncthreads();
            matvec<64, 128, 1>(Wout, sm.sd, sm.outv, tid); __syncthreads();

            // ---- state/prev update + emit ----
            if (tid < 128) sm.sfw[tid] = sm.vin[tid];  // sfw <- feat2s
            head = (head + 64) & 511;
            if (tid < 64) {
                float o = sm.outv[tid];
                sm.ring[(head + 448 + tid) & 511] = o;
                out[(long)b * OUT_PER_B + t * (NSUB * S) + k * S + tid] = o;
            }
            __syncthreads();
        }
    }
}

extern "C" void kernel_launch(void* const* d_in, const int* in_sizes, int n_in,
                              void* d_out, int out_size) {
    (void)in_sizes; (void)n_in; (void)out_size;
    const float* features = (const float*)d_in[0];
    const float* gfeat    = (const float*)d_in[1];
    const float* prev0    = (const float*)d_in[2];
    const float* Wc1  = (const float*)d_in[3];
    const float* Wc2  = (const float*)d_in[4];
    const float* Wc3  = (const float*)d_in[5];
    const float* Wfw  = (const float*)d_in[6];
    const float* Wfwg = (const float*)d_in[7];
    const float* Wih1 = (const float*)d_in[8];
    const float* Whh1 = (const float*)d_in[9];
    const float* Wih2 = (const float*)d_in[10];
    const float* Whh2 = (const float*)d_in[11];
    const float* Wih3 = (const float*)d_in[12];
    const float* Whh3 = (const float*)d_in[13];
    const float* Wg1  = (const float*)d_in[14];
    const float* Wg2  = (const float*)d_in[15];
    const float* Wg3  = (const float*)d_in[16];
    const float* Wsg  = (const float*)d_in[17];
    const float* Wsd  = (const float*)d_in[18];
    const float* Wout = (const float*)d_in[19];

    fargan_kernel<<<BATCH, NT>>>(features, gfeat, prev0,
                                 Wc1, Wc2, Wc3, Wfw, Wfwg,
                                 Wih1, Whh1, Wih2, Whh2, Wih3, Whh3,
                                 Wg1, Wg2, Wg3, Wsg, Wsd, Wout,
                                 (float*)d_out);
}

// round 7
// speedup vs baseline: 2.8493x; 2.8493x over previous
#include <cuda_runtime.h>
#include <math.h>

// FARGAN vocoder on GB300.
// Kernel 1 (cond): precompute per-frame conditioning c = tanh(tanh(tanh(x@Wc1)@Wc2)@Wc3)
//   for all (b, t) — embarrassingly parallel, weights reused across a frame tile.
// Kernel 2 (recur): serial 100x4 subframe recurrence, one CTA per batch element;
//   coalesced multi-lane matvecs, hot small weights cached in padded smem.

#define NT 256

namespace {
constexpr int S      = 64;
constexpr int L      = 512;
constexpr int F      = 193;
constexpr int BATCH  = 64;
constexpr int FRAMES = 100;
constexpr int NSUB   = 4;
constexpr int OUT_PER_B = FRAMES * NSUB * S;  // 25600

// conditioning prepass tiling
constexpr int TFRM   = 20;                 // frames per tile
constexpr int NTILES = FRAMES / TFRM;      // 5

// padded smem weight row strides, in float4 units (pad +1 f4 to dodge bank conflicts)
constexpr int FWG4 = 17;   // 64/4 + 1
constexpr int G4   = 17;
constexpr int OUT4 = 33;   // 128/4 + 1
constexpr int SG4  = 33;

constexpr int W_FWG_F4 = 64 * FWG4;
constexpr int W_G_F4   = 64 * G4;
constexpr int W_OUT_F4 = 64 * OUT4;
constexpr int W_SG_F4  = 128 * SG4;

struct SmemAct {
    float ring[512];   // previous-samples ring buffer
    float c[512];      // this frame's conditioning (loaded from scratch)
    float vin[388];    // [feat2s 128 | prev_sub 64 | lookback 68 | sfw 128]
    float fwt[64];
    float gi[192];
    float gh[192];
    float xg[128];     // [cur 64 | prev_sub 64]
    float skip[320];   // [o1 | o2 | o3 | fw | prev_sub]
    float sd[128];
    float sd2[128];
    float s1[64], s2[64], s3[64];
    float sfw[128];
};

constexpr size_t SMEM_BYTES =
    sizeof(SmemAct) + (size_t)(W_FWG_F4 + 3 * W_G_F4 + W_OUT_F4 + W_SG_F4) * 16;

struct CondSmem {
    float x [TFRM][256];
    float c1[TFRM][256];
    float c2[TFRM][256];
};
constexpr size_t COND_SMEM_BYTES = sizeof(CondSmem);  // 61,440 B
}

// conditioning scratch: c[b][t][512]
__device__ float g_cond[(size_t)BATCH * FRAMES * 512];

__device__ __forceinline__ float sigm(float v) {
    return 1.0f / (1.0f + __expf(-v));
}

// ---------------------------------------------------------------------------
// Kernel 1: conditioning prepass. grid = (BATCH, NTILES), block = 256.
// ---------------------------------------------------------------------------
__global__ void __launch_bounds__(NT, 1)
cond_kernel(const float* __restrict__ features,
            const float* __restrict__ gfeat,
            const float* __restrict__ Wc1,
            const float* __restrict__ Wc2,
            const float* __restrict__ Wc3) {
    extern __shared__ char raw[];
    CondSmem& cs = *reinterpret_cast<CondSmem*>(raw);
    const int b   = blockIdx.x;
    const int t0  = blockIdx.y * TFRM;
    const int tid = threadIdx.x;
    const float* featb = features + (long)b * F * FRAMES;

    // load x tile: x[t][i] = feat[i][t0+t] for i<192, else gfeat
    for (int idx = tid; idx < TFRM * 256; idx += NT) {
        int t = idx >> 8;
        int i = idx & 255;
        cs.x[t][i] = (i < 192) ? featb[i * FRAMES + (t0 + t)]
                               : gfeat[b * 64 + (i - 192)];
    }
    __syncthreads();

    // layer 1: c1[t][row] = tanh(sum_i Wc1[row][i] * x[t][i]); row = tid
    {
        const float4* __restrict__ W4 = reinterpret_cast<const float4*>(Wc1) + tid * 64;
        float acc[TFRM];
        #pragma unroll
        for (int t = 0; t < TFRM; t++) acc[t] = 0.f;
        #pragma unroll 4
        for (int j = 0; j < 64; j++) {
            float4 w = W4[j];
            #pragma unroll
            for (int t = 0; t < TFRM; t++) {
                const float4 a = reinterpret_cast<const float4*>(cs.x[t])[j];
                acc[t] += w.x * a.x + w.y * a.y + w.z * a.z + w.w * a.w;
            }
        }
        #pragma unroll
        for (int t = 0; t < TFRM; t++) cs.c1[t][tid] = tanhf(acc[t]);
    }
    __syncthreads();

    // layer 2: c2 = tanh(c1 @ Wc2^T)
    {
        const float4* __restrict__ W4 = reinterpret_cast<const float4*>(Wc2) + tid * 64;
        float acc[TFRM];
        #pragma unroll
        for (int t = 0; t < TFRM; t++) acc[t] = 0.f;
        #pragma unroll 4
        for (int j = 0; j < 64; j++) {
            float4 w = W4[j];
            #pragma unroll
            for (int t = 0; t < TFRM; t++) {
                const float4 a = reinterpret_cast<const float4*>(cs.c1[t])[j];
                acc[t] += w.x * a.x + w.y * a.y + w.z * a.z + w.w * a.w;
            }
        }
        #pragma unroll
        for (int t = 0; t < TFRM; t++) cs.c2[t][tid] = tanhf(acc[t]);
    }
    __syncthreads();

    // layer 3: c = tanh(c2 @ Wc3^T), 512 rows -> 2 rows per thread
    {
        const float4* __restrict__ W4a = reinterpret_cast<const float4*>(Wc3) + tid * 64;
        const float4* __restrict__ W4b = W4a + 256 * 64;
        float acc0[TFRM], acc1[TFRM];
        #pragma unroll
        for (int t = 0; t < TFRM; t++) { acc0[t] = 0.f; acc1[t] = 0.f; }
        #pragma unroll 2
        for (int j = 0; j < 64; j++) {
            float4 wa = W4a[j];
            float4 wb = W4b[j];
            #pragma unroll
            for (int t = 0; t < TFRM; t++) {
                const float4 a = reinterpret_cast<const float4*>(cs.c2[t])[j];
                acc0[t] += wa.x * a.x + wa.y * a.y + wa.z * a.z + wa.w * a.w;
                acc1[t] += wb.x * a.x + wb.y * a.y + wb.z * a.z + wb.w * a.w;
            }
        }
        #pragma unroll
        for (int t = 0; t < TFRM; t++) {
            float* dst = g_cond + ((long)b * FRAMES + (t0 + t)) * 512;
            dst[tid]       = tanhf(acc0[t]);
            dst[tid + 256] = tanhf(acc1[t]);
        }
    }
}

// ---------------------------------------------------------------------------
// matvec: out-row epilogue gets (row, dot). W viewed as float4 rows, stride
// STR4 (f4 units). P lanes cooperate per row, consecutive f4s per lane group.
// ---------------------------------------------------------------------------
template<int O, int I, int P, int STR4, class Epi>
__device__ __forceinline__ void matvec(const float* __restrict__ W,
                                       const float* __restrict__ v,
                                       int tid, Epi epi) {
    constexpr int NV    = I / 4;
    constexpr int RPP   = NT / P;
    constexpr int NPASS = O / RPP;
    constexpr int NITER = (NV + P - 1) / P;
    const float4* __restrict__ W4 = reinterpret_cast<const float4*>(W);
    const float4* __restrict__ v4 = reinterpret_cast<const float4*>(v);
    const int part  = tid & (P - 1);
    const int rbase = tid / P;

    #pragma unroll
    for (int p = 0; p < NPASS; p++) {
        const int row = p * RPP + rbase;
        const float4* __restrict__ wr = W4 + row * STR4;
        float4 acc = make_float4(0.f, 0.f, 0.f, 0.f);
        #pragma unroll
        for (int it = 0; it < NITER; it++) {
            const int j = part + it * P;
            if ((NV % P == 0) || (j < NV)) {
                float4 w = wr[j];
                float4 a = v4[j];
                acc.x += w.x * a.x;
                acc.y += w.y * a.y;
                acc.z += w.z * a.z;
                acc.w += w.w * a.w;
            }
        }
        float s = (acc.x + acc.y) + (acc.z + acc.w);
        #pragma unroll
        for (int m = 1; m < P; m <<= 1)
            s += __shfl_xor_sync(0xffffffffu, s, m);
        if (part == 0) epi(row, s);
    }
}

// copy a dense (O x I) fp32 gmem matrix into smem with padded row stride PAD4 (f4 units)
template<int O, int I, int PAD4>
__device__ __forceinline__ void stage(const float* __restrict__ W,
                                      float4* __restrict__ dst, int tid) {
    constexpr int NV = I / 4;
    const float4* __restrict__ src = reinterpret_cast<const float4*>(W);
    for (int k = tid; k < O * NV; k += NT) {
        int r = k / NV;
        int j = k - r * NV;
        dst[r * PAD4 + j] = src[k];
    }
}

// ---------------------------------------------------------------------------
// Kernel 2: serial recurrence. grid = BATCH, block = 256.
// ---------------------------------------------------------------------------
__global__ void __launch_bounds__(NT, 1)
fargan_kernel(const float* __restrict__ features,
              const float* __restrict__ prev0,
              const float* __restrict__ Wfw,
              const float* __restrict__ Wfwg, const float* __restrict__ Wih1,
              const float* __restrict__ Whh1, const float* __restrict__ Wih2,
              const float* __restrict__ Whh2, const float* __restrict__ Wih3,
              const float* __restrict__ Whh3, const float* __restrict__ Wg1,
              const float* __restrict__ Wg2,  const float* __restrict__ Wg3,
              const float* __restrict__ Wsg,  const float* __restrict__ Wsd,
              const float* __restrict__ Wout,
              float* __restrict__ out) {
    extern __shared__ char raw[];
    SmemAct& sm = *reinterpret_cast<SmemAct*>(raw);
    float4* wbase = reinterpret_cast<float4*>(raw + sizeof(SmemAct));
    float4* w_fwg = wbase;
    float4* w_g1  = w_fwg + W_FWG_F4;
    float4* w_g2  = w_g1 + W_G_F4;
    float4* w_g3  = w_g2 + W_G_F4;
    float4* w_out = w_g3 + W_G_F4;
    float4* w_sg  = w_out + W_OUT_F4;

    const int b   = blockIdx.x;
    const int tid = threadIdx.x;

    // stage hot weights into smem (once)
    stage<64, 64, FWG4>(Wfwg, w_fwg, tid);
    stage<64, 64, G4>  (Wg1,  w_g1,  tid);
    stage<64, 64, G4>  (Wg2,  w_g2,  tid);
    stage<64, 64, G4>  (Wg3,  w_g3,  tid);
    stage<64, 128, OUT4>(Wout, w_out, tid);
    stage<128, 128, SG4>(Wsg,  w_sg,  tid);

    // init state
    for (int i = tid; i < 512; i += NT) sm.ring[i] = prev0[b * 512 + i];
    if (tid < 64) { sm.s1[tid] = 0.f; sm.s2[tid] = 0.f; sm.s3[tid] = 0.f; }
    if (tid < 128) sm.sfw[tid] = 0.f;
    int head = 0;
    __syncthreads();

    const float* featb = features + (long)b * F * FRAMES;
    const float* condb = g_cond + (long)b * FRAMES * 512;
    float* outb = out + (long)b * OUT_PER_B;
    const float* wfwg_f = reinterpret_cast<const float*>(w_fwg);
    const float* wg_f[3] = { reinterpret_cast<const float*>(w_g1),
                             reinterpret_cast<const float*>(w_g2),
                             reinterpret_cast<const float*>(w_g3) };
    const float* wout_f = reinterpret_cast<const float*>(w_out);
    const float* wsg_f  = reinterpret_cast<const float*>(w_sg);
    const float* Wih[3] = { Wih1, Wih2, Wih3 };
    const float* Whh[3] = { Whh1, Whh2, Whh3 };
    float* st[3] = { sm.s1, sm.s2, sm.s3 };

    for (int t = 0; t < FRAMES; t++) {
        // load precomputed frame conditioning (2 floats/thread, coalesced)
        sm.c[tid]       = condb[t * 512 + tid];
        sm.c[tid + 256] = condb[t * 512 + tid + 256];
        const int period = __float2int_rn(featb[192 * FRAMES + t]);
        __syncthreads();

        for (int k = 0; k < NSUB; k++) {
            // ---- A: build vin, update sfw ----
            if (tid < 128) {
                float f = sm.c[tid * 4 + k];
                sm.vin[tid]       = f;
                sm.vin[260 + tid] = sm.sfw[tid];
                sm.sfw[tid]       = f;
            }
            if (tid < 64) {
                float p = sm.ring[(head + 448 + tid) & 511];
                sm.vin[128 + tid]  = p;
                sm.xg[64 + tid]    = p;
                sm.skip[256 + tid] = p;
            }
            if (tid >= 64 && tid < 132) {
                int i = tid - 64;
                int idx = L - period + i - 2;
                if (idx >= L) idx -= period;
                sm.vin[192 + i] = sm.ring[(head + idx) & 511];
            }
            __syncthreads();

            // ---- B: fwt = tanh(Wfw @ vin) ----
            matvec<64, 388, 8, 97>(Wfw, sm.vin, tid,
                [&](int r, float s) { sm.fwt[r] = tanhf(s); });
            __syncthreads();

            // ---- C: fw = fwt * sigm(Wfwg @ fwt)  (smem weights) ----
            matvec<64, 64, 4, FWG4>(wfwg_f, sm.fwt, tid,
                [&](int r, float s) {
                    float fw = sm.fwt[r] * sigm(s);
                    sm.xg[r]         = fw;
                    sm.skip[192 + r] = fw;
                });
            __syncthreads();

            // ---- three GRU + GLU stages ----
            #pragma unroll
            for (int g = 0; g < 3; g++) {
                float* state = st[g];
                matvec<192, 128, 4, 32>(Wih[g], sm.xg, tid,
                    [&](int r, float s) { sm.gi[r] = s; });
                matvec<192, 64, 4, 16>(Whh[g], state, tid,
                    [&](int r, float s) { sm.gh[r] = s; });
                __syncthreads();
                if (tid < 64) {
                    float r = sigm(sm.gi[tid]        + sm.gh[tid]);
                    float z = sigm(sm.gi[64 + tid]   + sm.gh[64 + tid]);
                    float n = tanhf(sm.gi[128 + tid] + r * sm.gh[128 + tid]);
                    state[tid] = (1.0f - z) * n + z * state[tid];
                }
                __syncthreads();
                matvec<64, 64, 4, G4>(wg_f[g], state, tid,
                    [&](int r, float s) {
                        float o = state[r] * sigm(s);
                        sm.skip[g * 64 + r] = o;
                        sm.xg[r] = o;
                    });
                __syncthreads();
            }

            // ---- G: sd = tanh(Wsd @ skip) ----
            matvec<128, 320, 8, 80>(Wsd, sm.skip, tid,
                [&](int r, float s) { sm.sd[r] = tanhf(s); });
            __syncthreads();

            // ---- H: sd2 = sd * sigm(Wsg @ sd)  (smem weights) ----
            matvec<128, 128, 2, SG4>(wsg_f, sm.sd, tid,
                [&](int r, float s) { sm.sd2[r] = sm.sd[r] * sigm(s); });
            __syncthreads();

            // ---- I: out = tanh(Wout @ sd2); write ring + gmem ----
            matvec<64, 128, 4, OUT4>(wout_f, sm.sd2, tid,
                [&](int r, float s) {
                    float o = tanhf(s);
                    sm.ring[(head + r) & 511] = o;   // == new_head+448+r (mod 512)
                    outb[t * (NSUB * S) + k * S + r] = o;
                });
            __syncthreads();
            head = (head + 64) & 511;
        }
    }
}

extern "C" void kernel_launch(void* const* d_in, const int* in_sizes, int n_in,
                              void* d_out, int out_size) {
    (void)in_sizes; (void)n_in; (void)out_size;
    const float* features = (const float*)d_in[0];
    const float* gfeat    = (const float*)d_in[1];
    const float* prev0    = (const float*)d_in[2];
    const float* Wc1  = (const float*)d_in[3];
    const float* Wc2  = (const float*)d_in[4];
    const float* Wc3  = (const float*)d_in[5];
    const float* Wfw  = (const float*)d_in[6];
    const float* Wfwg = (const float*)d_in[7];
    const float* Wih1 = (const float*)d_in[8];
    const float* Whh1 = (const float*)d_in[9];
    const float* Wih2 = (const float*)d_in[10];
    const float* Whh2 = (const float*)d_in[11];
    const float* Wih3 = (const float*)d_in[12];
    const float* Whh3 = (const float*)d_in[13];
    const float* Wg1  = (const float*)d_in[14];
    const float* Wg2  = (const float*)d_in[15];
    const float* Wg3  = (const float*)d_in[16];
    const float* Wsg  = (const float*)d_in[17];
    const float* Wsd  = (const float*)d_in[18];
    const float* Wout = (const float*)d_in[19];

    // Unconditional (idempotent; no static guards allowed in kernel_launch).
    cudaFuncSetAttribute(cond_kernel,
                         cudaFuncAttributeMaxDynamicSharedMemorySize,
                         (int)COND_SMEM_BYTES);
    cudaFuncSetAttribute(fargan_kernel,
                         cudaFuncAttributeMaxDynamicSharedMemorySize,
                         (int)SMEM_BYTES);

    dim3 cgrid(BATCH, NTILES);
    cond_kernel<<<cgrid, NT, COND_SMEM_BYTES>>>(features, gfeat, Wc1, Wc2, Wc3);
    fargan_kernel<<<BATCH, NT, SMEM_BYTES>>>(features, prev0,
                                             Wfw, Wfwg,
                                             Wih1, Whh1, Wih2, Whh2, Wih3, Whh3,
                                             Wg1, Wg2, Wg3, Wsg, Wsd, Wout,
                                             (float*)d_out);
}

// round 8
// speedup vs baseline: 3.2933x; 1.1558x over previous
#include <cuda_runtime.h>
#include <math.h>

// FARGAN vocoder on GB300.
// Kernel 1 (cond): parallel conditioning prepass (unchanged from round-5, NT=256).
// Kernel 2 (recur): serial recurrence, one CTA of 512 threads per batch element.
//   NT=512 halves per-thread weight footprint (no spills), P=8 lanes/row keeps
//   gmem loads coalesced, hot small weights resident in padded smem.

#define NT  512   // recurrence kernel block
#define NTC 256   // conditioning kernel block

namespace {
constexpr int S      = 64;
constexpr int L      = 512;
constexpr int F      = 193;
constexpr int BATCH  = 64;
constexpr int FRAMES = 100;
constexpr int NSUB   = 4;
constexpr int OUT_PER_B = FRAMES * NSUB * S;  // 25600

// conditioning prepass tiling
constexpr int TFRM   = 20;
constexpr int NTILES = FRAMES / TFRM;      // 5

// padded smem weight row strides, in float4 units
constexpr int FWG4 = 17;   // 64/4 + 1
constexpr int G4   = 17;
constexpr int OUT4 = 33;   // 128/4 + 1
constexpr int SG4  = 33;

constexpr int W_FWG_F4 = 64 * FWG4;
constexpr int W_G_F4   = 64 * G4;
constexpr int W_OUT_F4 = 64 * OUT4;
constexpr int W_SG_F4  = 128 * SG4;

struct SmemAct {
    float ring[512];
    float c[512];
    float vin[388];    // [feat2s 128 | prev_sub 64 | lookback 68 | sfw 128]
    float fwt[64];
    float gi[192];
    float gh[192];
    float xg[128];
    float skip[320];   // [o1 | o2 | o3 | fw | prev_sub]
    float sd[128];
    float sd2[128];
    float s1[64], s2[64], s3[64];
    float sfw[128];
};

constexpr size_t SMEM_BYTES =
    sizeof(SmemAct) + (size_t)(W_FWG_F4 + 3 * W_G_F4 + W_OUT_F4 + W_SG_F4) * 16;

struct CondSmem {
    float x [TFRM][256];
    float c1[TFRM][256];
    float c2[TFRM][256];
};
constexpr size_t COND_SMEM_BYTES = sizeof(CondSmem);
}

// conditioning scratch: c[b][t][512]
__device__ float g_cond[(size_t)BATCH * FRAMES * 512];

__device__ __forceinline__ float sigm(float v) {
    return 1.0f / (1.0f + __expf(-v));
}

// ---------------------------------------------------------------------------
// Kernel 1: conditioning prepass. grid = (BATCH, NTILES), block = 256.
// ---------------------------------------------------------------------------
__global__ void __launch_bounds__(NTC, 1)
cond_kernel(const float* __restrict__ features,
            const float* __restrict__ gfeat,
            const float* __restrict__ Wc1,
            const float* __restrict__ Wc2,
            const float* __restrict__ Wc3) {
    extern __shared__ char raw[];
    CondSmem& cs = *reinterpret_cast<CondSmem*>(raw);
    const int b   = blockIdx.x;
    const int t0  = blockIdx.y * TFRM;
    const int tid = threadIdx.x;
    const float* featb = features + (long)b * F * FRAMES;

    for (int idx = tid; idx < TFRM * 256; idx += NTC) {
        int t = idx >> 8;
        int i = idx & 255;
        cs.x[t][i] = (i < 192) ? featb[i * FRAMES + (t0 + t)]
                               : gfeat[b * 64 + (i - 192)];
    }
    __syncthreads();

    {
        const float4* __restrict__ W4 = reinterpret_cast<const float4*>(Wc1) + tid * 64;
        float acc[TFRM];
        #pragma unroll
        for (int t = 0; t < TFRM; t++) acc[t] = 0.f;
        #pragma unroll 4
        for (int j = 0; j < 64; j++) {
            float4 w = W4[j];
            #pragma unroll
            for (int t = 0; t < TFRM; t++) {
                const float4 a = reinterpret_cast<const float4*>(cs.x[t])[j];
                acc[t] += w.x * a.x + w.y * a.y + w.z * a.z + w.w * a.w;
            }
        }
        #pragma unroll
        for (int t = 0; t < TFRM; t++) cs.c1[t][tid] = tanhf(acc[t]);
    }
    __syncthreads();

    {
        const float4* __restrict__ W4 = reinterpret_cast<const float4*>(Wc2) + tid * 64;
        float acc[TFRM];
        #pragma unroll
        for (int t = 0; t < TFRM; t++) acc[t] = 0.f;
        #pragma unroll 4
        for (int j = 0; j < 64; j++) {
            float4 w = W4[j];
            #pragma unroll
            for (int t = 0; t < TFRM; t++) {
                const float4 a = reinterpret_cast<const float4*>(cs.c1[t])[j];
                acc[t] += w.x * a.x + w.y * a.y + w.z * a.z + w.w * a.w;
            }
        }
        #pragma unroll
        for (int t = 0; t < TFRM; t++) cs.c2[t][tid] = tanhf(acc[t]);
    }
    __syncthreads();

    {
        const float4* __restrict__ W4a = reinterpret_cast<const float4*>(Wc3) + tid * 64;
        const float4* __restrict__ W4b = W4a + 256 * 64;
        float acc0[TFRM], acc1[TFRM];
        #pragma unroll
        for (int t = 0; t < TFRM; t++) { acc0[t] = 0.f; acc1[t] = 0.f; }
        #pragma unroll 2
        for (int j = 0; j < 64; j++) {
            float4 wa = W4a[j];
            float4 wb = W4b[j];
            #pragma unroll
            for (int t = 0; t < TFRM; t++) {
                const float4 a = reinterpret_cast<const float4*>(cs.c2[t])[j];
                acc0[t] += wa.x * a.x + wa.y * a.y + wa.z * a.z + wa.w * a.w;
                acc1[t] += wb.x * a.x + wb.y * a.y + wb.z * a.z + wb.w * a.w;
            }
        }
        #pragma unroll
        for (int t = 0; t < TFRM; t++) {
            float* dst = g_cond + ((long)b * FRAMES + (t0 + t)) * 512;
            dst[tid]       = tanhf(acc0[t]);
            dst[tid + 256] = tanhf(acc1[t]);
        }
    }
}

// ---------------------------------------------------------------------------
// matvec for the recurrence kernel (block = NT = 512).
// P lanes per row read consecutive float4s (coalesced). Epilogue on lane 0.
// ---------------------------------------------------------------------------
template<int O, int I, int P, int STR4, class Epi>
__device__ __forceinline__ void matvec(const float* __restrict__ W,
                                       const float* __restrict__ v,
                                       int tid, Epi epi) {
    constexpr int NV    = I / 4;
    constexpr int RPP   = NT / P;            // rows per pass
    constexpr int NPASS = (O + RPP - 1) / RPP;
    constexpr int NITER = (NV + P - 1) / P;
    static_assert(O % RPP == 0 || NPASS == 1, "row partition");
    const float4* __restrict__ W4 = reinterpret_cast<const float4*>(W);
    const float4* __restrict__ v4 = reinterpret_cast<const float4*>(v);
    const int part  = tid & (P - 1);
    const int rbase = tid / P;

    #pragma unroll
    for (int p = 0; p < NPASS; p++) {
        const int row = p * RPP + rbase;
        if ((O % RPP != 0) && row >= O) break;
        const float4* __restrict__ wr = W4 + row * STR4;
        float4 acc = make_float4(0.f, 0.f, 0.f, 0.f);
        #pragma unroll
        for (int it = 0; it < NITER; it++) {
            const int j = part + it * P;
            if ((NV % P == 0) || (j < NV)) {
                float4 w = wr[j];
                float4 a = v4[j];
                acc.x += w.x * a.x;
                acc.y += w.y * a.y;
                acc.z += w.z * a.z;
                acc.w += w.w * a.w;
            }
        }
        float s = (acc.x + acc.y) + (acc.z + acc.w);
        #pragma unroll
        for (int m = 1; m < P; m <<= 1)
            s += __shfl_xor_sync(0xffffffffu, s, m);
        if (part == 0) epi(row, s);
    }
}

// copy (O x I) fp32 gmem matrix into smem with padded row stride PAD4 (f4 units)
template<int O, int I, int PAD4>
__device__ __forceinline__ void stage(const float* __restrict__ W,
                                      float4* __restrict__ dst, int tid) {
    constexpr int NV = I / 4;
    const float4* __restrict__ src = reinterpret_cast<const float4*>(W);
    for (int k = tid; k < O * NV; k += NT) {
        int r = k / NV;
        int j = k - r * NV;
        dst[r * PAD4 + j] = src[k];
    }
}

// ---------------------------------------------------------------------------
// Kernel 2: serial recurrence. grid = BATCH, block = 512.
// ---------------------------------------------------------------------------
__global__ void __launch_bounds__(NT, 1)
fargan_kernel(const float* __restrict__ features,
              const float* __restrict__ prev0,
              const float* __restrict__ Wfw,
              const float* __restrict__ Wfwg, const float* __restrict__ Wih1,
              const float* __restrict__ Whh1, const float* __restrict__ Wih2,
              const float* __restrict__ Whh2, const float* __restrict__ Wih3,
              const float* __restrict__ Whh3, const float* __restrict__ Wg1,
              const float* __restrict__ Wg2,  const float* __restrict__ Wg3,
              const float* __restrict__ Wsg,  const float* __restrict__ Wsd,
              const float* __restrict__ Wout,
              float* __restrict__ out) {
    extern __shared__ char raw[];
    SmemAct& sm = *reinterpret_cast<SmemAct*>(raw);
    float4* wbase = reinterpret_cast<float4*>(raw + sizeof(SmemAct));
    float4* w_fwg = wbase;
    float4* w_g1  = w_fwg + W_FWG_F4;
    float4* w_g2  = w_g1 + W_G_F4;
    float4* w_g3  = w_g2 + W_G_F4;
    float4* w_out = w_g3 + W_G_F4;
    float4* w_sg  = w_out + W_OUT_F4;

    const int b   = blockIdx.x;
    const int tid = threadIdx.x;

    stage<64, 64, FWG4>(Wfwg, w_fwg, tid);
    stage<64, 64, G4>  (Wg1,  w_g1,  tid);
    stage<64, 64, G4>  (Wg2,  w_g2,  tid);
    stage<64, 64, G4>  (Wg3,  w_g3,  tid);
    stage<64, 128, OUT4>(Wout, w_out, tid);
    stage<128, 128, SG4>(Wsg,  w_sg,  tid);

    for (int i = tid; i < 512; i += NT) sm.ring[i] = prev0[b * 512 + i];
    if (tid < 64) { sm.s1[tid] = 0.f; sm.s2[tid] = 0.f; sm.s3[tid] = 0.f; }
    if (tid < 128) sm.sfw[tid] = 0.f;
    int head = 0;
    __syncthreads();

    const float* featb = features + (long)b * F * FRAMES;
    const float* condb = g_cond + (long)b * FRAMES * 512;
    float* outb = out + (long)b * OUT_PER_B;
    const float* wfwg_f = reinterpret_cast<const float*>(w_fwg);
    const float* wg_f[3] = { reinterpret_cast<const float*>(w_g1),
                             reinterpret_cast<const float*>(w_g2),
                             reinterpret_cast<const float*>(w_g3) };
    const float* wout_f = reinterpret_cast<const float*>(w_out);
    const float* wsg_f  = reinterpret_cast<const float*>(w_sg);
    const float* Wih[3] = { Wih1, Wih2, Wih3 };
    const float* Whh[3] = { Whh1, Whh2, Whh3 };
    float* st[3] = { sm.s1, sm.s2, sm.s3 };

    for (int t = 0; t < FRAMES; t++) {
        if (tid < 512) sm.c[tid] = condb[t * 512 + tid];
        const int period = __float2int_rn(featb[192 * FRAMES + t]);
        __syncthreads();

        for (int k = 0; k < NSUB; k++) {
            // ---- A: build vin, update sfw ----
            if (tid < 128) {
                float f = sm.c[tid * 4 + k];
                sm.vin[tid]       = f;
                sm.vin[260 + tid] = sm.sfw[tid];
                sm.sfw[tid]       = f;
            }
            if (tid >= 128 && tid < 192) {
                int i = tid - 128;
                float p = sm.ring[(head + 448 + i) & 511];
                sm.vin[128 + i]  = p;
                sm.xg[64 + i]    = p;
                sm.skip[256 + i] = p;
            }
            if (tid >= 192 && tid < 260) {
                int i = tid - 192;
                int idx = L - period + i - 2;
                if (idx >= L) idx -= period;
                sm.vin[192 + i] = sm.ring[(head + idx) & 511];
            }
            __syncthreads();

            // ---- B: fwt = tanh(Wfw @ vin) ----  (64x388 gmem, P=8)
            matvec<64, 388, 8, 97>(Wfw, sm.vin, tid,
                [&](int r, float s) { sm.fwt[r] = tanhf(s); });
            __syncthreads();

            // ---- C: fw = fwt * sigm(Wfwg @ fwt)  (smem) ----
            matvec<64, 64, 8, FWG4>(wfwg_f, sm.fwt, tid,
                [&](int r, float s) {
                    float fw = sm.fwt[r] * sigm(s);
                    sm.xg[r]         = fw;
                    sm.skip[192 + r] = fw;
                });
            __syncthreads();

            // ---- three GRU + GLU stages ----
            #pragma unroll
            for (int g = 0; g < 3; g++) {
                float* state = st[g];
                // gi (192x128) and gh (192x64), both gmem P=8, back-to-back
                matvec<192, 128, 8, 32>(Wih[g], sm.xg, tid,
                    [&](int r, float s) { sm.gi[r] = s; });
                matvec<192, 64, 8, 16>(Whh[g], state, tid,
                    [&](int r, float s) { sm.gh[r] = s; });
                __syncthreads();
                if (tid < 64) {
                    float r = sigm(sm.gi[tid]        + sm.gh[tid]);
                    float z = sigm(sm.gi[64 + tid]   + sm.gh[64 + tid]);
                    float n = tanhf(sm.gi[128 + tid] + r * sm.gh[128 + tid]);
                    state[tid] = (1.0f - z) * n + z * state[tid];
                }
                __syncthreads();
                matvec<64, 64, 8, G4>(wg_f[g], state, tid,
                    [&](int r, float s) {
                        float o = state[r] * sigm(s);
                        sm.skip[g * 64 + r] = o;
                        sm.xg[r] = o;
                    });
                __syncthreads();
            }

            // ---- G: sd = tanh(Wsd @ skip) ----  (128x320 gmem, P=8)
            matvec<128, 320, 8, 80>(Wsd, sm.skip, tid,
                [&](int r, float s) { sm.sd[r] = tanhf(s); });
            __syncthreads();

            // ---- H: sd2 = sd * sigm(Wsg @ sd)  (smem) ----
            matvec<128, 128, 8, SG4>(wsg_f, sm.sd, tid,
                [&](int r, float s) { sm.sd2[r] = sm.sd[r] * sigm(s); });
            __syncthreads();

            // ---- I: out = tanh(Wout @ sd2); write ring + gmem ----
            matvec<64, 128, 8, OUT4>(wout_f, sm.sd2, tid,
                [&](int r, float s) {
                    float o = tanhf(s);
                    sm.ring[(head + r) & 511] = o;   // == new_head+448+r (mod 512)
                    outb[t * (NSUB * S) + k * S + r] = o;
                });
            __syncthreads();
            head = (head + 64) & 511;
        }
    }
}

extern "C" void kernel_launch(void* const* d_in, const int* in_sizes, int n_in,
                              void* d_out, int out_size) {
    (void)in_sizes; (void)n_in; (void)out_size;
    const float* features = (const float*)d_in[0];
    const float* gfeat    = (const float*)d_in[1];
    const float* prev0    = (const float*)d_in[2];
    const float* Wc1  = (const float*)d_in[3];
    const float* Wc2  = (const float*)d_in[4];
    const float* Wc3  = (const float*)d_in[5];
    const float* Wfw  = (const float*)d_in[6];
    const float* Wfwg = (const float*)d_in[7];
    const float* Wih1 = (const float*)d_in[8];
    const float* Whh1 = (const float*)d_in[9];
    const float* Wih2 = (const float*)d_in[10];
    const float* Whh2 = (const float*)d_in[11];
    const float* Wih3 = (const float*)d_in[12];
    const float* Whh3 = (const float*)d_in[13];
    const float* Wg1  = (const float*)d_in[14];
    const float* Wg2  = (const float*)d_in[15];
    const float* Wg3  = (const float*)d_in[16];
    const float* Wsg  = (const float*)d_in[17];
    const float* Wsd  = (const float*)d_in[18];
    const float* Wout = (const float*)d_in[19];

    cudaFuncSetAttribute(cond_kernel,
                         cudaFuncAttributeMaxDynamicSharedMemorySize,
                         (int)COND_SMEM_BYTES);
    cudaFuncSetAttribute(fargan_kernel,
                         cudaFuncAttributeMaxDynamicSharedMemorySize,
                         (int)SMEM_BYTES);

    dim3 cgrid(BATCH, NTILES);
    cond_kernel<<<cgrid, NTC, COND_SMEM_BYTES>>>(features, gfeat, Wc1, Wc2, Wc3);
    fargan_kernel<<<BATCH, NT, SMEM_BYTES>>>(features, prev0,
                                             Wfw, Wfwg,
                                             Wih1, Whh1, Wih2, Whh2, Wih3, Whh3,
                                             Wg1, Wg2, Wg3, Wsg, Wsd, Wout,
                                             (float*)d_out);
}